// round 13
// baseline (speedup 1.0000x reference)
#include <cuda_runtime.h>
#include <cstdint>

// Problem constants
#define B_  4
#define S_  2048
#define D_  768
#define H_  12
#define DK_ 64
#define M_  (B_ * S_)   // 8192

// Scratch (module-static device memory; no runtime allocation)
// Pre-converted tf32 bit copies of inputs / weights:
__device__ uint32_t g_q32[(size_t)M_ * D_];
__device__ uint32_t g_k32[(size_t)M_ * D_];
__device__ uint32_t g_v32[(size_t)M_ * D_];
__device__ uint32_t g_Wq32[(size_t)D_ * D_];
__device__ uint32_t g_Wk32[(size_t)D_ * D_];
__device__ uint32_t g_Wv32[(size_t)D_ * D_];
__device__ uint32_t g_Wo32[(size_t)D_ * D_];
// Q,K as tf32 bits [b,h,s,dk]; V as tf32 bits TRANSPOSED [b,h,dk,s];
// C (attn output, concat layout) as tf32 bits [b,s,d].
__device__ uint32_t g_Q[(size_t)B_ * H_ * S_ * DK_];
__device__ uint32_t g_K[(size_t)B_ * H_ * S_ * DK_];
__device__ uint32_t g_V[(size_t)B_ * H_ * DK_ * S_];
__device__ uint32_t g_C[(size_t)M_ * D_];

// ---------------------------------------------------------------------------
// Helpers
// ---------------------------------------------------------------------------
__device__ __forceinline__ uint32_t f2tf(float f) {
    uint32_t r;
    asm("cvt.rna.tf32.f32 %0, %1;" : "=r"(r) : "f"(f));
    return r;
}
__device__ __forceinline__ float ex2f(float x) {
    float r;
    asm("ex2.approx.f32 %0, %1;" : "=f"(r) : "f"(x));
    return r;
}
// D += A(16x8 row) * B(8x8 col), tf32 inputs, fp32 accumulate
__device__ __forceinline__ void mma8(float* c, const uint32_t* a, const uint32_t* b) {
    asm volatile(
        "mma.sync.aligned.m16n8k8.row.col.f32.tf32.tf32.f32 "
        "{%0,%1,%2,%3},{%4,%5,%6,%7},{%8,%9},{%0,%1,%2,%3};"
        : "+f"(c[0]), "+f"(c[1]), "+f"(c[2]), "+f"(c[3])
        : "r"(a[0]), "r"(a[1]), "r"(a[2]), "r"(a[3]), "r"(b[0]), "r"(b[1]));
}
__device__ __forceinline__ uint32_t smem_u32(const void* p) {
    uint32_t a;
    asm("{ .reg .u64 t; cvta.to.shared.u64 t, %1; cvt.u32.u64 %0, t; }" : "=r"(a) : "l"(p));
    return a;
}
__device__ __forceinline__ void cpasync16(uint32_t dst, const void* src) {
    asm volatile("cp.async.cg.shared.global [%0], [%1], 16;" :: "r"(dst), "l"(src));
}
#define CP_COMMIT() asm volatile("cp.async.commit_group;" ::: "memory")
#define CP_WAIT0()  asm volatile("cp.async.wait_group 0;" ::: "memory")

// ---------------------------------------------------------------------------
// Pre-pass: convert fp32 arrays to tf32 bit patterns (one cvt per element,
// ever). z selects the array; grid-stride in float4/uint4 quads.
// ---------------------------------------------------------------------------
__global__ __launch_bounds__(256) void cvt_kernel(
    const float* __restrict__ q, const float* __restrict__ k,
    const float* __restrict__ v,
    const float* __restrict__ Wq, const float* __restrict__ Wk,
    const float* __restrict__ Wv, const float* __restrict__ Wo,
    uint32_t* __restrict__ oq, uint32_t* __restrict__ ok,
    uint32_t* __restrict__ ov,
    uint32_t* __restrict__ oWq, uint32_t* __restrict__ oWk,
    uint32_t* __restrict__ oWv, uint32_t* __restrict__ oWo)
{
    const int z = blockIdx.y;
    const float* src;
    uint32_t* dst;
    int n;
    switch (z) {
        case 0: src = q;  dst = oq;  n = M_ * D_; break;
        case 1: src = k;  dst = ok;  n = M_ * D_; break;
        case 2: src = v;  dst = ov;  n = M_ * D_; break;
        case 3: src = Wq; dst = oWq; n = D_ * D_; break;
        case 4: src = Wk; dst = oWk; n = D_ * D_; break;
        case 5: src = Wv; dst = oWv; n = D_ * D_; break;
        default: src = Wo; dst = oWo; n = D_ * D_; break;
    }
    const int stride = gridDim.x * blockDim.x * 4;
    for (int i = (blockIdx.x * blockDim.x + threadIdx.x) * 4; i < n; i += stride) {
        const float4 s = *(const float4*)(src + i);
        *(uint4*)(dst + i) = make_uint4(f2tf(s.x), f2tf(s.y), f2tf(s.z), f2tf(s.w));
    }
}

// ---------------------------------------------------------------------------
// GEMM core: acc = A[128 rows]@W[128 rows]^T over K=768, tf32 tensor cores.
// A and W are PRE-CONVERTED tf32 bits -> the mainloop is pure LDS+MMA.
// BM=128, BN=128, BK=32. 128 threads = 4 warps (2x2), warp tile 64x64.
// cp.async(.cg) double-buffered smem.
// ---------------------------------------------------------------------------
#define G_STR 36
#define G_ARR (128 * G_STR)        // words per A or B tile
#define G_BUF (2 * G_ARR)          // A + B per buffer

__device__ __forceinline__ void gemm_mainloop(
    const uint32_t* __restrict__ A, const uint32_t* __restrict__ W,
    uint32_t* smf, int m0, int n0, int tid, float acc[4][8][4])
{
    const uint32_t smem_base = smem_u32(smf);
    const int lane = tid & 31;
    const int wid  = tid >> 5;
    const int g    = lane >> 2;
    const int t4   = lane & 3;
    const int wm   = wid >> 1;
    const int wn   = wid & 1;
    const int ro = tid >> 3;          // 0..15
    const int ch = (tid & 7) * 4;     // 0..28 (words)

    auto issue = [&](int buf, int k0) {
#pragma unroll
        for (int i = 0; i < 8; i++) {
            const int r = ro + i * 16;
            cpasync16(smem_base + (buf * G_BUF + r * G_STR + ch) * 4,
                      A + (size_t)(m0 + r) * D_ + k0 + ch);
            cpasync16(smem_base + (buf * G_BUF + G_ARR + r * G_STR + ch) * 4,
                      W + (size_t)(n0 + r) * D_ + k0 + ch);
        }
    };

    issue(0, 0);
    CP_COMMIT();

    const int nC = D_ / 32;   // 24
    for (int c = 0; c < nC; c++) {
        CP_WAIT0();
        __syncthreads();
        if (c + 1 < nC) {
            issue((c + 1) & 1, (c + 1) * 32);
            CP_COMMIT();
        }

        const uint32_t* As = smf + (c & 1) * G_BUF;
        const uint32_t* Bs = As + G_ARR;

#pragma unroll
        for (int kf = 0; kf < 4; kf++) {
            uint32_t a[4][4];
#pragma unroll
            for (int mf = 0; mf < 4; mf++) {
                const int r = wm * 64 + mf * 16 + g;
                a[mf][0] = As[r * G_STR + kf * 8 + t4];
                a[mf][1] = As[(r + 8) * G_STR + kf * 8 + t4];
                a[mf][2] = As[r * G_STR + kf * 8 + t4 + 4];
                a[mf][3] = As[(r + 8) * G_STR + kf * 8 + t4 + 4];
            }
#pragma unroll
            for (int nf = 0; nf < 8; nf++) {
                uint32_t b[2];
                const int r = wn * 64 + nf * 8 + g;
                b[0] = Bs[r * G_STR + kf * 8 + t4];
                b[1] = Bs[r * G_STR + kf * 8 + t4 + 4];
#pragma unroll
                for (int mf = 0; mf < 4; mf++)
                    mma8(acc[mf][nf], a[mf], b);
            }
        }
    }
}

// Fused Q/K/V projection GEMM: blockIdx.z selects operand set.
// z=0,1 (Q,K): tf32 bits [b,h,s,dk];  z=2 (V): tf32 bits [b,h,dk,s].
__global__ __launch_bounds__(128, 2) void gemm_proj_kernel(
    const float* __restrict__ bq, const float* __restrict__ bk,
    const float* __restrict__ bv)
{
    extern __shared__ uint32_t smw[];
    const int z = blockIdx.z;
    const uint32_t* A    = (z == 0) ? g_q32  : (z == 1) ? g_k32  : g_v32;
    const uint32_t* W    = (z == 0) ? g_Wq32 : (z == 1) ? g_Wk32 : g_Wv32;
    const float*    bias = (z == 0) ? bq     : (z == 1) ? bk     : bv;
    uint32_t*       Cout = (z == 0) ? g_Q    : (z == 1) ? g_K    : g_V;

    const int tid = threadIdx.x;
    const int lane = tid & 31;
    const int g  = lane >> 2;
    const int t4 = lane & 3;
    const int wm = (tid >> 5) >> 1;
    const int wn = (tid >> 5) & 1;
    const int m0 = blockIdx.x * 128;
    const int n0 = blockIdx.y * 128;

    float acc[4][8][4] = {};
    gemm_mainloop(A, W, smw, m0, n0, tid, acc);

#pragma unroll
    for (int mf = 0; mf < 4; mf++) {
#pragma unroll
        for (int nf = 0; nf < 8; nf++) {
            const int n = n0 + wn * 64 + nf * 8 + 2 * t4;
            const float b0 = bias[n];
            const float b1 = bias[n + 1];
#pragma unroll
            for (int rr = 0; rr < 2; rr++) {
                const int m = m0 + wm * 64 + mf * 16 + g + rr * 8;
                const float ox = acc[mf][nf][2 * rr + 0] + b0;
                const float oy = acc[mf][nf][2 * rr + 1] + b1;
                const int bidx = m >> 11;
                const int srow = m & (S_ - 1);
                const int h    = n >> 6;
                const int dk   = n & 63;
                if (z < 2) {
                    *(uint2*)(Cout + (((size_t)(bidx * H_ + h)) * S_ + srow) * DK_ + dk) =
                        make_uint2(f2tf(ox), f2tf(oy));
                } else {
                    const size_t base = ((size_t)(bidx * H_ + h)) * DK_;
                    Cout[(base + dk) * S_ + srow]     = f2tf(ox);
                    Cout[(base + dk + 1) * S_ + srow] = f2tf(oy);
                }
            }
        }
    }
}

// Output projection GEMM: reads pre-converted C and Wo bits, fp32 out [M,N].
__global__ __launch_bounds__(128, 2) void gemm_out_kernel(
    const float* __restrict__ bias, float* __restrict__ Cout)
{
    extern __shared__ uint32_t smw[];
    const int tid = threadIdx.x;
    const int lane = tid & 31;
    const int g  = lane >> 2;
    const int t4 = lane & 3;
    const int wm = (tid >> 5) >> 1;
    const int wn = (tid >> 5) & 1;
    const int m0 = blockIdx.x * 128;
    const int n0 = blockIdx.y * 128;

    float acc[4][8][4] = {};
    gemm_mainloop(g_C, g_Wo32, smw, m0, n0, tid, acc);

#pragma unroll
    for (int mf = 0; mf < 4; mf++) {
#pragma unroll
        for (int nf = 0; nf < 8; nf++) {
            const int n = n0 + wn * 64 + nf * 8 + 2 * t4;
            const float b0 = bias[n];
            const float b1 = bias[n + 1];
#pragma unroll
            for (int rr = 0; rr < 2; rr++) {
                const int m = m0 + wm * 64 + mf * 16 + g + rr * 8;
                *(float2*)(Cout + (size_t)m * D_ + n) =
                    make_float2(acc[mf][nf][2 * rr + 0] + b0,
                                acc[mf][nf][2 * rr + 1] + b1);
            }
        }
    }
}

// ---------------------------------------------------------------------------
// Fused flash attention (tf32 mma.sync) — R10 known-good config.
// CTA: 256 queries x one (b,h). 8 warps x 32 query rows.
// K/V pre-converted tf32 (V pre-transposed): double-buffered cp.async tiles.
// P never touches smem (S-fragment -> A-fragment shuffle permute).
// Scores in log2 domain (log2e folded into Q scale); ex2 softmax.
// Epilogue writes tf32 BITS into g_C (consumed raw by gemm_out).
// Masked rows: scale 0 -> uniform softmax == reference (-1e9 rows).
// ---------------------------------------------------------------------------
#define TQ 256
#define TK 64
#define AT_STR 68
#define KV_WORDS (64 * AT_STR)
#define BUF_WORDS (2 * KV_WORDS)

__global__ __launch_bounds__(256, 1) void attn_kernel(const int* __restrict__ mask)
{
    extern __shared__ uint32_t sm[];

    const int tid  = threadIdx.x;
    const int lane = tid & 31;
    const int wid  = tid >> 5;
    const int g    = lane >> 2;
    const int t4   = lane & 3;
    const int q0   = blockIdx.x * TQ;
    const int bh   = blockIdx.y;
    const int b    = bh / H_;
    const int h    = bh - b * H_;

    const uint32_t* Qg = g_Q + (size_t)bh * S_ * DK_;
    const uint32_t* Kg = g_K + (size_t)bh * S_ * DK_;
    const uint32_t* Vg = g_V + (size_t)bh * DK_ * S_;

    const uint32_t smem_base = smem_u32(sm);

    const int crow = tid >> 2;
    const int ccol = (tid & 3) * 16;

    int row[2][2];
    float sc[2][2];
#pragma unroll
    for (int mb = 0; mb < 2; mb++)
#pragma unroll
        for (int rr = 0; rr < 2; rr++) {
            row[mb][rr] = wid * 32 + mb * 16 + g + rr * 8;
            sc[mb][rr] = mask[b * S_ + q0 + row[mb][rr]] ? 0.18033688011112042f : 0.0f;
        }

    uint32_t qa[8][2][4];
#pragma unroll
    for (int kf = 0; kf < 8; kf++)
#pragma unroll
        for (int mb = 0; mb < 2; mb++) {
            qa[kf][mb][0] = f2tf(__uint_as_float(Qg[(size_t)(q0 + row[mb][0]) * DK_ + kf * 8 + t4]) * sc[mb][0]);
            qa[kf][mb][1] = f2tf(__uint_as_float(Qg[(size_t)(q0 + row[mb][1]) * DK_ + kf * 8 + t4]) * sc[mb][1]);
            qa[kf][mb][2] = f2tf(__uint_as_float(Qg[(size_t)(q0 + row[mb][0]) * DK_ + kf * 8 + t4 + 4]) * sc[mb][0]);
            qa[kf][mb][3] = f2tf(__uint_as_float(Qg[(size_t)(q0 + row[mb][1]) * DK_ + kf * 8 + t4 + 4]) * sc[mb][1]);
        }

    float mr[2][2], l[2][2];
    float oacc[2][8][4] = {};
#pragma unroll
    for (int mb = 0; mb < 2; mb++)
#pragma unroll
        for (int rr = 0; rr < 2; rr++) { mr[mb][rr] = -1e30f; l[mb][rr] = 0.0f; }

    auto issue_tile = [&](int buf, int k0) {
        const uint32_t kdst = smem_base + (buf * BUF_WORDS + crow * AT_STR + ccol) * 4;
        const uint32_t vdst = kdst + KV_WORDS * 4;
        const uint32_t* ksrc = Kg + (size_t)(k0 + crow) * DK_ + ccol;
        const uint32_t* vsrc = Vg + (size_t)crow * S_ + k0 + ccol;
#pragma unroll
        for (int i = 0; i < 4; i++) {
            cpasync16(kdst + i * 16, ksrc + i * 4);
            cpasync16(vdst + i * 16, vsrc + i * 4);
        }
    };

    issue_tile(0, 0);
    CP_COMMIT();

    const int nT = S_ / TK;
    for (int t = 0; t < nT; t++) {
        CP_WAIT0();
        __syncthreads();
        if (t + 1 < nT) {
            issue_tile((t + 1) & 1, (t + 1) * TK);
            CP_COMMIT();
        }

        const uint32_t* Ks = sm + (t & 1) * BUF_WORDS;
        const uint32_t* Vt = Ks + KV_WORDS;

        float sacc[2][8][4] = {};
#pragma unroll
        for (int kf = 0; kf < 8; kf++) {
#pragma unroll
            for (int nf = 0; nf < 8; nf++) {
                uint32_t kb[2];
                const int rk = nf * 8 + g;
                kb[0] = Ks[rk * AT_STR + kf * 8 + t4];
                kb[1] = Ks[rk * AT_STR + kf * 8 + t4 + 4];
                mma8(sacc[0][nf], qa[kf][0], kb);
                mma8(sacc[1][nf], qa[kf][1], kb);
            }
        }

#pragma unroll
        for (int mb = 0; mb < 2; mb++) {
            float mx0 = -1e30f, mx1 = -1e30f;
#pragma unroll
            for (int nf = 0; nf < 8; nf++) {
                mx0 = fmaxf(mx0, fmaxf(sacc[mb][nf][0], sacc[mb][nf][1]));
                mx1 = fmaxf(mx1, fmaxf(sacc[mb][nf][2], sacc[mb][nf][3]));
            }
            mx0 = fmaxf(mx0, __shfl_xor_sync(0xffffffffu, mx0, 1));
            mx0 = fmaxf(mx0, __shfl_xor_sync(0xffffffffu, mx0, 2));
            mx1 = fmaxf(mx1, __shfl_xor_sync(0xffffffffu, mx1, 1));
            mx1 = fmaxf(mx1, __shfl_xor_sync(0xffffffffu, mx1, 2));

            const float mn0 = fmaxf(mr[mb][0], mx0);
            const float mn1 = fmaxf(mr[mb][1], mx1);
            const float c0 = ex2f(mr[mb][0] - mn0);
            const float c1 = ex2f(mr[mb][1] - mn1);
            mr[mb][0] = mn0; mr[mb][1] = mn1;

            float s0 = 0.0f, s1 = 0.0f;
#pragma unroll
            for (int nf = 0; nf < 8; nf++) {
                sacc[mb][nf][0] = ex2f(sacc[mb][nf][0] - mn0);
                sacc[mb][nf][1] = ex2f(sacc[mb][nf][1] - mn0);
                sacc[mb][nf][2] = ex2f(sacc[mb][nf][2] - mn1);
                sacc[mb][nf][3] = ex2f(sacc[mb][nf][3] - mn1);
                s0 += sacc[mb][nf][0] + sacc[mb][nf][1];
                s1 += sacc[mb][nf][2] + sacc[mb][nf][3];
            }
            s0 += __shfl_xor_sync(0xffffffffu, s0, 1);
            s0 += __shfl_xor_sync(0xffffffffu, s0, 2);
            s1 += __shfl_xor_sync(0xffffffffu, s1, 1);
            s1 += __shfl_xor_sync(0xffffffffu, s1, 2);
            l[mb][0] = l[mb][0] * c0 + s0;
            l[mb][1] = l[mb][1] * c1 + s1;

#pragma unroll
            for (int nf = 0; nf < 8; nf++) {
                oacc[mb][nf][0] *= c0; oacc[mb][nf][1] *= c0;
                oacc[mb][nf][2] *= c1; oacc[mb][nf][3] *= c1;
            }
        }

        const int srcA = (lane & ~3) | (t4 >> 1);
        const int srcB = srcA + 2;
        const bool odd = (t4 & 1);
#pragma unroll
        for (int kf = 0; kf < 8; kf++) {
            uint32_t pa[2][4];
#pragma unroll
            for (int mb = 0; mb < 2; mb++) {
                const float c0 = sacc[mb][kf][0], c1 = sacc[mb][kf][1];
                const float c2 = sacc[mb][kf][2], c3 = sacc[mb][kf][3];
                const float u0A = __shfl_sync(0xffffffffu, c0, srcA);
                const float u1A = __shfl_sync(0xffffffffu, c1, srcA);
                const float u2A = __shfl_sync(0xffffffffu, c2, srcA);
                const float u3A = __shfl_sync(0xffffffffu, c3, srcA);
                const float u0B = __shfl_sync(0xffffffffu, c0, srcB);
                const float u1B = __shfl_sync(0xffffffffu, c1, srcB);
                const float u2B = __shfl_sync(0xffffffffu, c2, srcB);
                const float u3B = __shfl_sync(0xffffffffu, c3, srcB);
                pa[mb][0] = f2tf(odd ? u1A : u0A);
                pa[mb][1] = f2tf(odd ? u3A : u2A);
                pa[mb][2] = f2tf(odd ? u1B : u0B);
                pa[mb][3] = f2tf(odd ? u3B : u2B);
            }
#pragma unroll
            for (int nf = 0; nf < 8; nf++) {
                uint32_t vb[2];
                vb[0] = Vt[(nf * 8 + g) * AT_STR + kf * 8 + t4];
                vb[1] = Vt[(nf * 8 + g) * AT_STR + kf * 8 + t4 + 4];
                mma8(oacc[0][nf], pa[0], vb);
                mma8(oacc[1][nf], pa[1], vb);
            }
        }
    }

    // Epilogue: normalize, write tf32 BITS in concat [b, s, d] layout
#pragma unroll
    for (int mb = 0; mb < 2; mb++) {
        const float inv0 = 1.0f / l[mb][0];
        const float inv1 = 1.0f / l[mb][1];
        const size_t base0 = ((size_t)b * S_ + q0 + row[mb][0]) * D_ + h * DK_;
        const size_t base1 = ((size_t)b * S_ + q0 + row[mb][1]) * D_ + h * DK_;
#pragma unroll
        for (int nf = 0; nf < 8; nf++) {
            *(uint2*)(g_C + base0 + nf * 8 + 2 * t4) =
                make_uint2(f2tf(oacc[mb][nf][0] * inv0), f2tf(oacc[mb][nf][1] * inv0));
            *(uint2*)(g_C + base1 + nf * 8 + 2 * t4) =
                make_uint2(f2tf(oacc[mb][nf][2] * inv1), f2tf(oacc[mb][nf][3] * inv1));
        }
    }
}

// ---------------------------------------------------------------------------
extern "C" void kernel_launch(void* const* d_in, const int* in_sizes, int n_in,
                              void* d_out, int out_size)
{
    const float* q    = (const float*)d_in[0];
    const float* k    = (const float*)d_in[1];
    const float* v    = (const float*)d_in[2];
    const int*   mask = (const int*)  d_in[3];
    const float* Wq   = (const float*)d_in[4];
    const float* bq   = (const float*)d_in[5];
    const float* Wk   = (const float*)d_in[6];
    const float* bk   = (const float*)d_in[7];
    const float* Wv   = (const float*)d_in[8];
    const float* bv   = (const float*)d_in[9];
    const float* Wo   = (const float*)d_in[10];
    const float* bo   = (const float*)d_in[11];
    float* out = (float*)d_out;

    void *pq32, *pk32, *pv32, *pWq, *pWk, *pWv, *pWo;
    cudaGetSymbolAddress(&pq32, g_q32);
    cudaGetSymbolAddress(&pk32, g_k32);
    cudaGetSymbolAddress(&pv32, g_v32);
    cudaGetSymbolAddress(&pWq, g_Wq32);
    cudaGetSymbolAddress(&pWk, g_Wk32);
    cudaGetSymbolAddress(&pWv, g_Wv32);
    cudaGetSymbolAddress(&pWo, g_Wo32);

    const int gemm_smem = 2 * G_BUF * (int)sizeof(uint32_t);  // 73728 B
    cudaFuncSetAttribute(gemm_proj_kernel, cudaFuncAttributeMaxDynamicSharedMemorySize, gemm_smem);
    cudaFuncSetAttribute(gemm_out_kernel,  cudaFuncAttributeMaxDynamicSharedMemorySize, gemm_smem);

    // Pre-pass: one-time tf32 conversion of inputs + weights
    cvt_kernel<<<dim3(3072, 7), dim3(256)>>>(
        q, k, v, Wq, Wk, Wv, Wo,
        (uint32_t*)pq32, (uint32_t*)pk32, (uint32_t*)pv32,
        (uint32_t*)pWq, (uint32_t*)pWk, (uint32_t*)pWv, (uint32_t*)pWo);

    // Fused Q/K/V projections (one launch; cvt-free mainloop)
    gemm_proj_kernel<<<dim3(M_ / 128, D_ / 128, 3), dim3(128), gemm_smem>>>(bq, bk, bv);

    // Fused attention -> concat layout (tf32 bits)
    const int smem = 2 * BUF_WORDS * (int)sizeof(uint32_t);  // 69632 B
    cudaFuncSetAttribute(attn_kernel, cudaFuncAttributeMaxDynamicSharedMemorySize, smem);
    attn_kernel<<<dim3(S_ / TQ, B_ * H_), dim3(256), smem>>>(mask);

    // Output projection (cvt-free mainloop)
    gemm_out_kernel<<<dim3(M_ / 128, D_ / 128), dim3(128), gemm_smem>>>(bo, out);
}

// round 14
// speedup vs baseline: 1.8849x; 1.8849x over previous
#include <cuda_runtime.h>
#include <cuda_fp16.h>
#include <cstdint>

// Problem constants
#define B_  4
#define S_  2048
#define D_  768
#define H_  12
#define DK_ 64
#define M_  (B_ * S_)   // 8192
#define DW  (D_ / 2)    // 384 words (half-pairs) per row

// Scratch (module-static device memory; no runtime allocation)
// Pre-converted fp16 copies (packed half2 per uint32):
__device__ uint32_t g_q16[(size_t)M_ * DW];
__device__ uint32_t g_k16[(size_t)M_ * DW];
__device__ uint32_t g_v16[(size_t)M_ * DW];
__device__ uint32_t g_Wq16[(size_t)D_ * DW];
__device__ uint32_t g_Wk16[(size_t)D_ * DW];
__device__ uint32_t g_Wv16[(size_t)D_ * DW];
__device__ uint32_t g_Wo16[(size_t)D_ * DW];
// Q,K fp16 [b,h,s,dk]; V fp16 TRANSPOSED [b,h,dk,s]; C fp16 concat [b,s,d].
__device__ uint32_t g_Q[(size_t)B_ * H_ * S_ * DK_ / 2];
__device__ uint32_t g_K[(size_t)B_ * H_ * S_ * DK_ / 2];
__device__ uint32_t g_V[(size_t)B_ * H_ * DK_ * S_ / 2];
__device__ uint32_t g_C[(size_t)M_ * DW];

// ---------------------------------------------------------------------------
// Helpers
// ---------------------------------------------------------------------------
__device__ __forceinline__ uint32_t f2h2(float a, float b) {
    __half2 h = __floats2half2_rn(a, b);   // low = a, high = b
    return *(uint32_t*)&h;
}
__device__ __forceinline__ float ex2f(float x) {
    float r;
    asm("ex2.approx.f32 %0, %1;" : "=f"(r) : "f"(x));
    return r;
}
// D += A(16x16 row) * B(16x8 col), fp16 inputs, fp32 accumulate
__device__ __forceinline__ void mma16(float* c, const uint32_t* a, const uint32_t* b) {
    asm volatile(
        "mma.sync.aligned.m16n8k16.row.col.f32.f16.f16.f32 "
        "{%0,%1,%2,%3},{%4,%5,%6,%7},{%8,%9},{%0,%1,%2,%3};"
        : "+f"(c[0]), "+f"(c[1]), "+f"(c[2]), "+f"(c[3])
        : "r"(a[0]), "r"(a[1]), "r"(a[2]), "r"(a[3]), "r"(b[0]), "r"(b[1]));
}
__device__ __forceinline__ uint32_t smem_u32(const void* p) {
    uint32_t a;
    asm("{ .reg .u64 t; cvta.to.shared.u64 t, %1; cvt.u32.u64 %0, t; }" : "=r"(a) : "l"(p));
    return a;
}
__device__ __forceinline__ void cpasync16(uint32_t dst, const void* src) {
    asm volatile("cp.async.cg.shared.global [%0], [%1], 16;" :: "r"(dst), "l"(src));
}
#define CP_COMMIT() asm volatile("cp.async.commit_group;" ::: "memory")
#define CP_WAIT0()  asm volatile("cp.async.wait_group 0;" ::: "memory")

// ---------------------------------------------------------------------------
// Pre-pass: fp32 -> packed fp16. blockIdx.y selects array.
// ---------------------------------------------------------------------------
__global__ __launch_bounds__(256) void cvt_kernel(
    const float* __restrict__ q, const float* __restrict__ k,
    const float* __restrict__ v,
    const float* __restrict__ Wq, const float* __restrict__ Wk,
    const float* __restrict__ Wv, const float* __restrict__ Wo)
{
    const int z = blockIdx.y;
    const float* src;
    uint32_t* dst;
    int n;
    switch (z) {
        case 0: src = q;  dst = g_q16;  n = M_ * D_; break;
        case 1: src = k;  dst = g_k16;  n = M_ * D_; break;
        case 2: src = v;  dst = g_v16;  n = M_ * D_; break;
        case 3: src = Wq; dst = g_Wq16; n = D_ * D_; break;
        case 4: src = Wk; dst = g_Wk16; n = D_ * D_; break;
        case 5: src = Wv; dst = g_Wv16; n = D_ * D_; break;
        default: src = Wo; dst = g_Wo16; n = D_ * D_; break;
    }
    const int stride = gridDim.x * blockDim.x * 4;
    for (int i = (blockIdx.x * blockDim.x + threadIdx.x) * 4; i < n; i += stride) {
        const float4 s = *(const float4*)(src + i);
        *(uint2*)(dst + i / 2) = make_uint2(f2h2(s.x, s.y), f2h2(s.z, s.w));
    }
}

// ---------------------------------------------------------------------------
// fp16 GEMM core: acc = A[128 rows]@W[128 rows]^T over K=768.
// BM=128, BN=128, BK=64 halves (32 words), 12 chunks. 128 threads = 4 warps
// (2x2), warp tile 64x64. cp.async(.cg) double-buffered. Tile rows stride 36
// words (32 data + 4 pad) -> conflict-free fragment loads (4g+t4 mod 32).
// ---------------------------------------------------------------------------
#define G_STR 36
#define G_ARR (128 * G_STR)        // words per A or B tile
#define G_BUF (2 * G_ARR)          // A + B per buffer

__device__ __forceinline__ void gemm_mainloop(
    const uint32_t* __restrict__ A, const uint32_t* __restrict__ W,
    uint32_t* smf, int m0, int n0, int tid, float acc[4][8][4])
{
    const uint32_t smem_base = smem_u32(smf);
    const int lane = tid & 31;
    const int wid  = tid >> 5;
    const int g    = lane >> 2;
    const int t4   = lane & 3;
    const int wm   = wid >> 1;
    const int wn   = wid & 1;
    const int ro = tid >> 3;          // 0..15
    const int ch = (tid & 7) * 4;     // 0..28 (words)

    auto issue = [&](int buf, int k0w) {
#pragma unroll
        for (int i = 0; i < 8; i++) {
            const int r = ro + i * 16;
            cpasync16(smem_base + (buf * G_BUF + r * G_STR + ch) * 4,
                      A + (size_t)(m0 + r) * DW + k0w + ch);
            cpasync16(smem_base + (buf * G_BUF + G_ARR + r * G_STR + ch) * 4,
                      W + (size_t)(n0 + r) * DW + k0w + ch);
        }
    };

    issue(0, 0);
    CP_COMMIT();

    const int nC = 12;
    for (int c = 0; c < nC; c++) {
        CP_WAIT0();
        __syncthreads();
        if (c + 1 < nC) {
            issue((c + 1) & 1, (c + 1) * 32);
            CP_COMMIT();
        }

        const uint32_t* As = smf + (c & 1) * G_BUF;
        const uint32_t* Bs = As + G_ARR;

#pragma unroll
        for (int kf = 0; kf < 4; kf++) {
            uint32_t a[4][4];
#pragma unroll
            for (int mf = 0; mf < 4; mf++) {
                const int r = wm * 64 + mf * 16 + g;
                a[mf][0] = As[r * G_STR + kf * 8 + t4];
                a[mf][1] = As[(r + 8) * G_STR + kf * 8 + t4];
                a[mf][2] = As[r * G_STR + kf * 8 + t4 + 4];
                a[mf][3] = As[(r + 8) * G_STR + kf * 8 + t4 + 4];
            }
#pragma unroll
            for (int nf = 0; nf < 8; nf++) {
                uint32_t b[2];
                const int r = wn * 64 + nf * 8 + g;
                b[0] = Bs[r * G_STR + kf * 8 + t4];
                b[1] = Bs[r * G_STR + kf * 8 + t4 + 4];
#pragma unroll
                for (int mf = 0; mf < 4; mf++)
                    mma16(acc[mf][nf], a[mf], b);
            }
        }
    }
}

// Fused Q/K/V projection: z selects operand set.
// z=0,1 (Q,K): fp16 [b,h,s,dk]; z=2 (V): fp16 [b,h,dk,s].
__global__ __launch_bounds__(128, 2) void gemm_proj_kernel(
    const float* __restrict__ bq, const float* __restrict__ bk,
    const float* __restrict__ bv)
{
    extern __shared__ uint32_t smw[];
    const int z = blockIdx.z;
    const uint32_t* A    = (z == 0) ? g_q16  : (z == 1) ? g_k16  : g_v16;
    const uint32_t* W    = (z == 0) ? g_Wq16 : (z == 1) ? g_Wk16 : g_Wv16;
    const float*    bias = (z == 0) ? bq     : (z == 1) ? bk     : bv;
    uint32_t*       Cout = (z == 0) ? g_Q    : (z == 1) ? g_K    : g_V;

    const int tid = threadIdx.x;
    const int lane = tid & 31;
    const int g  = lane >> 2;
    const int t4 = lane & 3;
    const int wm = (tid >> 5) >> 1;
    const int wn = (tid >> 5) & 1;
    const int m0 = blockIdx.x * 128;
    const int n0 = blockIdx.y * 128;

    float acc[4][8][4] = {};
    gemm_mainloop(A, W, smw, m0, n0, tid, acc);

#pragma unroll
    for (int mf = 0; mf < 4; mf++) {
#pragma unroll
        for (int nf = 0; nf < 8; nf++) {
            const int n = n0 + wn * 64 + nf * 8 + 2 * t4;
            const float b0 = bias[n];
            const float b1 = bias[n + 1];
#pragma unroll
            for (int rr = 0; rr < 2; rr++) {
                const int m = m0 + wm * 64 + mf * 16 + g + rr * 8;
                const float ox = acc[mf][nf][2 * rr + 0] + b0;
                const float oy = acc[mf][nf][2 * rr + 1] + b1;
                const int bidx = m >> 11;
                const int srow = m & (S_ - 1);
                const int h    = n >> 6;
                const int dk   = n & 63;
                if (z < 2) {
                    Cout[(((size_t)(bidx * H_ + h)) * S_ + srow) * (DK_ / 2) + dk / 2] =
                        f2h2(ox, oy);
                } else {
                    __half* Vh = (__half*)Cout;
                    const size_t base = ((size_t)(bidx * H_ + h)) * DK_;
                    Vh[(base + dk) * S_ + srow]     = __float2half_rn(ox);
                    Vh[(base + dk + 1) * S_ + srow] = __float2half_rn(oy);
                }
            }
        }
    }
}

// Output projection: reads fp16 C and Wo, fp32 out [M, D].
__global__ __launch_bounds__(128, 2) void gemm_out_kernel(
    const float* __restrict__ bias, float* __restrict__ Cout)
{
    extern __shared__ uint32_t smw[];
    const int tid = threadIdx.x;
    const int lane = tid & 31;
    const int g  = lane >> 2;
    const int t4 = lane & 3;
    const int wm = (tid >> 5) >> 1;
    const int wn = (tid >> 5) & 1;
    const int m0 = blockIdx.x * 128;
    const int n0 = blockIdx.y * 128;

    float acc[4][8][4] = {};
    gemm_mainloop(g_C, g_Wo16, smw, m0, n0, tid, acc);

#pragma unroll
    for (int mf = 0; mf < 4; mf++) {
#pragma unroll
        for (int nf = 0; nf < 8; nf++) {
            const int n = n0 + wn * 64 + nf * 8 + 2 * t4;
            const float b0 = bias[n];
            const float b1 = bias[n + 1];
#pragma unroll
            for (int rr = 0; rr < 2; rr++) {
                const int m = m0 + wm * 64 + mf * 16 + g + rr * 8;
                *(float2*)(Cout + (size_t)m * D_ + n) =
                    make_float2(acc[mf][nf][2 * rr + 0] + b0,
                                acc[mf][nf][2 * rr + 1] + b1);
            }
        }
    }
}

// ---------------------------------------------------------------------------
// Fused flash attention, fp16 m16n8k16.
// CTA: 256 queries x one (b,h). 8 warps x 32 query rows.
// fp16 halves MMA count AND the S->P permute vanishes: the m16n8k16
// A-fragment cols {2t4,2t4+1} coincide with the S-accumulator layout, so
// P operands are pure cvt.f16x2 register packs (no shuffles, no smem).
// K tile [key][d] halves, V transposed [d][key]; stride 36 words.
// Scores in log2 domain (log2e folded into Q scale); ex2 softmax.
// Epilogue writes fp16 C (consumed by gemm_out).
// Masked rows: scale 0 -> uniform softmax == reference (-1e9 rows).
// ---------------------------------------------------------------------------
#define TQ 256
#define TK 64
#define AT_STR 36
#define KV_WORDS (64 * AT_STR)             // 2304 words per K or V tile
#define BUF_WORDS (2 * KV_WORDS)           // K + V per buffer

__global__ __launch_bounds__(256, 1) void attn_kernel(const int* __restrict__ mask)
{
    extern __shared__ uint32_t sm[];

    const int tid  = threadIdx.x;
    const int lane = tid & 31;
    const int wid  = tid >> 5;
    const int g    = lane >> 2;
    const int t4   = lane & 3;
    const int q0   = blockIdx.x * TQ;
    const int bh   = blockIdx.y;
    const int b    = bh / H_;
    const int h    = bh - b * H_;

    const uint32_t* Qg = g_Q + (size_t)bh * S_ * (DK_ / 2);
    const uint32_t* Kg = g_K + (size_t)bh * S_ * (DK_ / 2);
    const uint32_t* Vg = g_V + (size_t)bh * DK_ * (S_ / 2);   // [dk][s/2]

    const uint32_t smem_base = smem_u32(sm);

    // copy mapping: 64 rows x 32 words per tile; 256 threads: 8 words each
    const int crow = tid >> 2;          // 0..63
    const int ccol = (tid & 3) * 8;     // 0,8,16,24

    int row[2][2];
    float sc[2][2];
#pragma unroll
    for (int mb = 0; mb < 2; mb++)
#pragma unroll
        for (int rr = 0; rr < 2; rr++) {
            row[mb][rr] = wid * 32 + mb * 16 + g + rr * 8;
            // 1/sqrt(64) * log2(e): scores land in log2 domain
            sc[mb][rr] = mask[b * S_ + q0 + row[mb][rr]] ? 0.18033688011112042f : 0.0f;
        }

    // Q fragments (fp16 pairs, scale folded in)
    uint32_t qa[4][2][4];
#pragma unroll
    for (int kf = 0; kf < 4; kf++)
#pragma unroll
        for (int mb = 0; mb < 2; mb++) {
#pragma unroll
            for (int rr = 0; rr < 2; rr++) {
                const uint32_t* qrow = Qg + (size_t)(q0 + row[mb][rr]) * (DK_ / 2);
                uint32_t w0 = qrow[kf * 8 + t4];
                uint32_t w1 = qrow[kf * 8 + t4 + 4];
                float2 f0 = __half22float2(*(__half2*)&w0);
                float2 f1 = __half22float2(*(__half2*)&w1);
                qa[kf][mb][rr]     = f2h2(f0.x * sc[mb][rr], f0.y * sc[mb][rr]);
                qa[kf][mb][rr + 2] = f2h2(f1.x * sc[mb][rr], f1.y * sc[mb][rr]);
            }
        }

    float mr[2][2], l[2][2];
    float oacc[2][8][4] = {};
#pragma unroll
    for (int mb = 0; mb < 2; mb++)
#pragma unroll
        for (int rr = 0; rr < 2; rr++) { mr[mb][rr] = -1e30f; l[mb][rr] = 0.0f; }

    auto issue_tile = [&](int buf, int k0) {
        const uint32_t kdst = smem_base + (buf * BUF_WORDS + crow * AT_STR + ccol) * 4;
        const uint32_t vdst = kdst + KV_WORDS * 4;
        const uint32_t* ksrc = Kg + (size_t)(k0 + crow) * (DK_ / 2) + ccol;
        const uint32_t* vsrc = Vg + (size_t)crow * (S_ / 2) + k0 / 2 + ccol;
        cpasync16(kdst, ksrc);
        cpasync16(kdst + 16, ksrc + 4);
        cpasync16(vdst, vsrc);
        cpasync16(vdst + 16, vsrc + 4);
    };

    issue_tile(0, 0);
    CP_COMMIT();

    const int nT = S_ / TK;
    for (int t = 0; t < nT; t++) {
        CP_WAIT0();
        __syncthreads();
        if (t + 1 < nT) {
            issue_tile((t + 1) & 1, (t + 1) * TK);
            CP_COMMIT();
        }

        const uint32_t* Ks = sm + (t & 1) * BUF_WORDS;
        const uint32_t* Vt = Ks + KV_WORDS;

        // S = Q @ K^T  (warp: 32 rows x 64 keys; 4 k16 steps)
        float sacc[2][8][4] = {};
#pragma unroll
        for (int kf = 0; kf < 4; kf++) {
#pragma unroll
            for (int nf = 0; nf < 8; nf++) {
                uint32_t kb[2];
                const int rk = nf * 8 + g;
                kb[0] = Ks[rk * AT_STR + kf * 8 + t4];
                kb[1] = Ks[rk * AT_STR + kf * 8 + t4 + 4];
                mma16(sacc[0][nf], qa[kf][0], kb);
                mma16(sacc[1][nf], qa[kf][1], kb);
            }
        }

        // Online softmax (log2 domain; quad reduce)
#pragma unroll
        for (int mb = 0; mb < 2; mb++) {
            float mx0 = -1e30f, mx1 = -1e30f;
#pragma unroll
            for (int nf = 0; nf < 8; nf++) {
                mx0 = fmaxf(mx0, fmaxf(sacc[mb][nf][0], sacc[mb][nf][1]));
                mx1 = fmaxf(mx1, fmaxf(sacc[mb][nf][2], sacc[mb][nf][3]));
            }
            mx0 = fmaxf(mx0, __shfl_xor_sync(0xffffffffu, mx0, 1));
            mx0 = fmaxf(mx0, __shfl_xor_sync(0xffffffffu, mx0, 2));
            mx1 = fmaxf(mx1, __shfl_xor_sync(0xffffffffu, mx1, 1));
            mx1 = fmaxf(mx1, __shfl_xor_sync(0xffffffffu, mx1, 2));

            const float mn0 = fmaxf(mr[mb][0], mx0);
            const float mn1 = fmaxf(mr[mb][1], mx1);
            const float c0 = ex2f(mr[mb][0] - mn0);
            const float c1 = ex2f(mr[mb][1] - mn1);
            mr[mb][0] = mn0; mr[mb][1] = mn1;

            float s0 = 0.0f, s1 = 0.0f;
#pragma unroll
            for (int nf = 0; nf < 8; nf++) {
                sacc[mb][nf][0] = ex2f(sacc[mb][nf][0] - mn0);
                sacc[mb][nf][1] = ex2f(sacc[mb][nf][1] - mn0);
                sacc[mb][nf][2] = ex2f(sacc[mb][nf][2] - mn1);
                sacc[mb][nf][3] = ex2f(sacc[mb][nf][3] - mn1);
                s0 += sacc[mb][nf][0] + sacc[mb][nf][1];
                s1 += sacc[mb][nf][2] + sacc[mb][nf][3];
            }
            s0 += __shfl_xor_sync(0xffffffffu, s0, 1);
            s0 += __shfl_xor_sync(0xffffffffu, s0, 2);
            s1 += __shfl_xor_sync(0xffffffffu, s1, 1);
            s1 += __shfl_xor_sync(0xffffffffu, s1, 2);
            l[mb][0] = l[mb][0] * c0 + s0;
            l[mb][1] = l[mb][1] * c1 + s1;

#pragma unroll
            for (int nf = 0; nf < 8; nf++) {
                oacc[mb][nf][0] *= c0; oacc[mb][nf][1] *= c0;
                oacc[mb][nf][2] *= c1; oacc[mb][nf][3] *= c1;
            }
        }

        // O += P @ V. fp16 A-fragment cols == S-accumulator cols: pure packs.
#pragma unroll
        for (int kf = 0; kf < 4; kf++) {
            uint32_t pa[2][4];
#pragma unroll
            for (int mb = 0; mb < 2; mb++) {
                pa[mb][0] = f2h2(sacc[mb][2 * kf][0],     sacc[mb][2 * kf][1]);
                pa[mb][1] = f2h2(sacc[mb][2 * kf][2],     sacc[mb][2 * kf][3]);
                pa[mb][2] = f2h2(sacc[mb][2 * kf + 1][0], sacc[mb][2 * kf + 1][1]);
                pa[mb][3] = f2h2(sacc[mb][2 * kf + 1][2], sacc[mb][2 * kf + 1][3]);
            }
#pragma unroll
            for (int nf = 0; nf < 8; nf++) {
                uint32_t vb[2];
                const int rv = nf * 8 + g;
                vb[0] = Vt[rv * AT_STR + kf * 8 + t4];
                vb[1] = Vt[rv * AT_STR + kf * 8 + t4 + 4];
                mma16(oacc[0][nf], pa[0], vb);
                mma16(oacc[1][nf], pa[1], vb);
            }
        }
    }

    // Epilogue: normalize, write fp16 pairs in concat [b, s, d] layout
#pragma unroll
    for (int mb = 0; mb < 2; mb++) {
        const float inv0 = 1.0f / l[mb][0];
        const float inv1 = 1.0f / l[mb][1];
        const size_t b0w = ((size_t)b * S_ + q0 + row[mb][0]) * DW + h * (DK_ / 2);
        const size_t b1w = ((size_t)b * S_ + q0 + row[mb][1]) * DW + h * (DK_ / 2);
#pragma unroll
        for (int nf = 0; nf < 8; nf++) {
            g_C[b0w + nf * 4 + t4] = f2h2(oacc[mb][nf][0] * inv0, oacc[mb][nf][1] * inv0);
            g_C[b1w + nf * 4 + t4] = f2h2(oacc[mb][nf][2] * inv1, oacc[mb][nf][3] * inv1);
        }
    }
}

// ---------------------------------------------------------------------------
extern "C" void kernel_launch(void* const* d_in, const int* in_sizes, int n_in,
                              void* d_out, int out_size)
{
    const float* q    = (const float*)d_in[0];
    const float* k    = (const float*)d_in[1];
    const float* v    = (const float*)d_in[2];
    const int*   mask = (const int*)  d_in[3];
    const float* bq   = (const float*)d_in[5];
    const float* bk   = (const float*)d_in[7];
    const float* bv   = (const float*)d_in[9];
    const float* bo   = (const float*)d_in[11];
    const float* Wq   = (const float*)d_in[4];
    const float* Wk   = (const float*)d_in[6];
    const float* Wv   = (const float*)d_in[8];
    const float* Wo   = (const float*)d_in[10];
    float* out = (float*)d_out;

    const int gemm_smem = 2 * G_BUF * (int)sizeof(uint32_t);  // 73728 B
    cudaFuncSetAttribute(gemm_proj_kernel, cudaFuncAttributeMaxDynamicSharedMemorySize, gemm_smem);
    cudaFuncSetAttribute(gemm_out_kernel,  cudaFuncAttributeMaxDynamicSharedMemorySize, gemm_smem);

    // Pre-pass: fp32 -> fp16 for inputs + weights
    cvt_kernel<<<dim3(2048, 7), dim3(256)>>>(q, k, v, Wq, Wk, Wv, Wo);

    // Fused Q/K/V projections (fp16 MMA)
    gemm_proj_kernel<<<dim3(M_ / 128, D_ / 128, 3), dim3(128), gemm_smem>>>(bq, bk, bv);

    // Fused attention (fp16 MMA) -> fp16 concat layout
    const int smem = 2 * BUF_WORDS * (int)sizeof(uint32_t);  // 36864 B
    cudaFuncSetAttribute(attn_kernel, cudaFuncAttributeMaxDynamicSharedMemorySize, smem);
    attn_kernel<<<dim3(S_ / TQ, B_ * H_), dim3(256), smem>>>(mask);

    // Output projection (fp16 MMA, fp32 out)
    gemm_out_kernel<<<dim3(M_ / 128, D_ / 128), dim3(128), gemm_smem>>>(bo, out);
}

// round 15
// speedup vs baseline: 1.9325x; 1.0253x over previous
#include <cuda_runtime.h>
#include <cuda_fp16.h>
#include <cstdint>

// Problem constants
#define B_  4
#define S_  2048
#define D_  768
#define H_  12
#define DK_ 64
#define M_  (B_ * S_)   // 8192
#define DW  (D_ / 2)    // 384 words (half-pairs) per row

// Scratch (module-static device memory; no runtime allocation)
// Pre-converted fp16 copies (packed half2 per uint32):
__device__ uint32_t g_q16[(size_t)M_ * DW];
__device__ uint32_t g_k16[(size_t)M_ * DW];
__device__ uint32_t g_v16[(size_t)M_ * DW];
__device__ uint32_t g_Wq16[(size_t)D_ * DW];
__device__ uint32_t g_Wk16[(size_t)D_ * DW];
__device__ uint32_t g_Wv16[(size_t)D_ * DW];
__device__ uint32_t g_Wo16[(size_t)D_ * DW];
// Q,K fp16 [b,h,s,dk]; V fp16 TRANSPOSED [b,h,dk,s]; C fp16 concat [b,s,d].
__device__ uint32_t g_Q[(size_t)B_ * H_ * S_ * DK_ / 2];
__device__ uint32_t g_K[(size_t)B_ * H_ * S_ * DK_ / 2];
__device__ uint32_t g_V[(size_t)B_ * H_ * DK_ * S_ / 2];
__device__ uint32_t g_C[(size_t)M_ * DW];

// ---------------------------------------------------------------------------
// Helpers
// ---------------------------------------------------------------------------
__device__ __forceinline__ uint32_t f2h2(float a, float b) {
    __half2 h = __floats2half2_rn(a, b);   // low = a, high = b
    return *(uint32_t*)&h;
}
__device__ __forceinline__ float ex2f(float x) {
    float r;
    asm("ex2.approx.f32 %0, %1;" : "=f"(r) : "f"(x));
    return r;
}
// D += A(16x16 row) * B(16x8 col), fp16 inputs, fp32 accumulate
__device__ __forceinline__ void mma16(float* c, const uint32_t* a, const uint32_t* b) {
    asm volatile(
        "mma.sync.aligned.m16n8k16.row.col.f32.f16.f16.f32 "
        "{%0,%1,%2,%3},{%4,%5,%6,%7},{%8,%9},{%0,%1,%2,%3};"
        : "+f"(c[0]), "+f"(c[1]), "+f"(c[2]), "+f"(c[3])
        : "r"(a[0]), "r"(a[1]), "r"(a[2]), "r"(a[3]), "r"(b[0]), "r"(b[1]));
}
__device__ __forceinline__ uint32_t smem_u32(const void* p) {
    uint32_t a;
    asm("{ .reg .u64 t; cvta.to.shared.u64 t, %1; cvt.u32.u64 %0, t; }" : "=r"(a) : "l"(p));
    return a;
}
__device__ __forceinline__ void cpasync16(uint32_t dst, const void* src) {
    asm volatile("cp.async.cg.shared.global [%0], [%1], 16;" :: "r"(dst), "l"(src));
}
#define CP_COMMIT() asm volatile("cp.async.commit_group;" ::: "memory")
#define CP_WAIT0()  asm volatile("cp.async.wait_group 0;" ::: "memory")

// ldmatrix: 4 / 2 m8n8 b16 matrices. Result distribution: within matrix m,
// lane l holds word (l&3) of row (l>>2) — matches our fragment indexing.
__device__ __forceinline__ void ldmx4(uint32_t* r, uint32_t addr) {
    asm volatile("ldmatrix.sync.aligned.m8n8.x4.shared.b16 {%0,%1,%2,%3}, [%4];"
                 : "=r"(r[0]), "=r"(r[1]), "=r"(r[2]), "=r"(r[3]) : "r"(addr));
}
__device__ __forceinline__ void ldmx2(uint32_t* r, uint32_t addr) {
    asm volatile("ldmatrix.sync.aligned.m8n8.x2.shared.b16 {%0,%1}, [%2];"
                 : "=r"(r[0]), "=r"(r[1]) : "r"(addr));
}

// ---------------------------------------------------------------------------
// Pre-pass: fp32 -> packed fp16. blockIdx.y selects array.
// ---------------------------------------------------------------------------
__global__ __launch_bounds__(256) void cvt_kernel(
    const float* __restrict__ q, const float* __restrict__ k,
    const float* __restrict__ v,
    const float* __restrict__ Wq, const float* __restrict__ Wk,
    const float* __restrict__ Wv, const float* __restrict__ Wo)
{
    const int z = blockIdx.y;
    const float* src;
    uint32_t* dst;
    int n;
    switch (z) {
        case 0: src = q;  dst = g_q16;  n = M_ * D_; break;
        case 1: src = k;  dst = g_k16;  n = M_ * D_; break;
        case 2: src = v;  dst = g_v16;  n = M_ * D_; break;
        case 3: src = Wq; dst = g_Wq16; n = D_ * D_; break;
        case 4: src = Wk; dst = g_Wk16; n = D_ * D_; break;
        case 5: src = Wv; dst = g_Wv16; n = D_ * D_; break;
        default: src = Wo; dst = g_Wo16; n = D_ * D_; break;
    }
    const int stride = gridDim.x * blockDim.x * 4;
    for (int i = (blockIdx.x * blockDim.x + threadIdx.x) * 4; i < n; i += stride) {
        const float4 s = *(const float4*)(src + i);
        *(uint2*)(dst + i / 2) = make_uint2(f2h2(s.x, s.y), f2h2(s.z, s.w));
    }
}

// ---------------------------------------------------------------------------
// fp16 GEMM core: acc = A[128 rows]@W[128 rows]^T over K=768.
// BM=128, BN=128, BK=64 halves (32 words), 12 chunks. 128 threads = 4 warps
// (2x2), warp tile 64x64. cp.async(.cg) double-buffered. Stride 36 words:
// ldmatrix-conflict-free (row stride == 4 banks). Fragments via ldmatrix.
// ---------------------------------------------------------------------------
#define G_STR 36
#define G_ARR (128 * G_STR)        // words per A or B tile
#define G_BUF (2 * G_ARR)          // A + B per buffer

__device__ __forceinline__ void gemm_mainloop(
    const uint32_t* __restrict__ A, const uint32_t* __restrict__ W,
    uint32_t* smf, int m0, int n0, int tid, float acc[4][8][4])
{
    const uint32_t smem_base = smem_u32(smf);
    const int lane = tid & 31;
    const int wid  = tid >> 5;
    const int wm   = wid >> 1;
    const int wn   = wid & 1;
    const int ro = tid >> 3;          // 0..15
    const int ch = (tid & 7) * 4;     // 0..28 (words)

    // ldmatrix per-lane addressing
    const int rowoff = lane & 7;
    const int sel    = lane >> 3;          // 0..3 (x4: matrix index)
    const int selb   = sel & 1;            // x2: matrix index

    auto issue = [&](int buf, int k0w) {
#pragma unroll
        for (int i = 0; i < 8; i++) {
            const int r = ro + i * 16;
            cpasync16(smem_base + (buf * G_BUF + r * G_STR + ch) * 4,
                      A + (size_t)(m0 + r) * DW + k0w + ch);
            cpasync16(smem_base + (buf * G_BUF + G_ARR + r * G_STR + ch) * 4,
                      W + (size_t)(n0 + r) * DW + k0w + ch);
        }
    };

    issue(0, 0);
    CP_COMMIT();

    const int nC = 12;
    for (int c = 0; c < nC; c++) {
        CP_WAIT0();
        __syncthreads();
        if (c + 1 < nC) {
            issue((c + 1) & 1, (c + 1) * 32);
            CP_COMMIT();
        }

        const uint32_t abase = smem_base + ((c & 1) * G_BUF) * 4;
        const uint32_t bbase = abase + G_ARR * 4;

#pragma unroll
        for (int kf = 0; kf < 4; kf++) {
            uint32_t a[4][4];
#pragma unroll
            for (int mf = 0; mf < 4; mf++) {
                const int r = wm * 64 + mf * 16 + (sel & 1) * 8 + rowoff;
                ldmx4(a[mf], abase + ((uint32_t)(r * G_STR + kf * 8 + (sel >> 1) * 4)) * 4);
            }
            uint32_t bf[8][2];
#pragma unroll
            for (int nf = 0; nf < 8; nf++) {
                const int r = wn * 64 + nf * 8 + rowoff;
                ldmx2(bf[nf], bbase + ((uint32_t)(r * G_STR + kf * 8 + selb * 4)) * 4);
            }
#pragma unroll
            for (int nf = 0; nf < 8; nf++)
#pragma unroll
                for (int mf = 0; mf < 4; mf++)
                    mma16(acc[mf][nf], a[mf], bf[nf]);
        }
    }
}

// Fused Q/K/V projection: z selects operand set.
// z=0,1 (Q,K): fp16 [b,h,s,dk]; z=2 (V): fp16 [b,h,dk,s].
__global__ __launch_bounds__(128, 2) void gemm_proj_kernel(
    const float* __restrict__ bq, const float* __restrict__ bk,
    const float* __restrict__ bv)
{
    extern __shared__ uint32_t smw[];
    const int z = blockIdx.z;
    const uint32_t* A    = (z == 0) ? g_q16  : (z == 1) ? g_k16  : g_v16;
    const uint32_t* W    = (z == 0) ? g_Wq16 : (z == 1) ? g_Wk16 : g_Wv16;
    const float*    bias = (z == 0) ? bq     : (z == 1) ? bk     : bv;
    uint32_t*       Cout = (z == 0) ? g_Q    : (z == 1) ? g_K    : g_V;

    const int tid = threadIdx.x;
    const int lane = tid & 31;
    const int g  = lane >> 2;
    const int t4 = lane & 3;
    const int wm = (tid >> 5) >> 1;
    const int wn = (tid >> 5) & 1;
    const int m0 = blockIdx.x * 128;
    const int n0 = blockIdx.y * 128;

    float acc[4][8][4] = {};
    gemm_mainloop(A, W, smw, m0, n0, tid, acc);

#pragma unroll
    for (int mf = 0; mf < 4; mf++) {
#pragma unroll
        for (int nf = 0; nf < 8; nf++) {
            const int n = n0 + wn * 64 + nf * 8 + 2 * t4;
            const float b0 = bias[n];
            const float b1 = bias[n + 1];
#pragma unroll
            for (int rr = 0; rr < 2; rr++) {
                const int m = m0 + wm * 64 + mf * 16 + g + rr * 8;
                const float ox = acc[mf][nf][2 * rr + 0] + b0;
                const float oy = acc[mf][nf][2 * rr + 1] + b1;
                const int bidx = m >> 11;
                const int srow = m & (S_ - 1);
                const int h    = n >> 6;
                const int dk   = n & 63;
                if (z < 2) {
                    Cout[(((size_t)(bidx * H_ + h)) * S_ + srow) * (DK_ / 2) + dk / 2] =
                        f2h2(ox, oy);
                } else {
                    __half* Vh = (__half*)Cout;
                    const size_t base = ((size_t)(bidx * H_ + h)) * DK_;
                    Vh[(base + dk) * S_ + srow]     = __float2half_rn(ox);
                    Vh[(base + dk + 1) * S_ + srow] = __float2half_rn(oy);
                }
            }
        }
    }
}

// Output projection: reads fp16 C and Wo, fp32 out [M, D].
__global__ __launch_bounds__(128, 2) void gemm_out_kernel(
    const float* __restrict__ bias, float* __restrict__ Cout)
{
    extern __shared__ uint32_t smw[];
    const int tid = threadIdx.x;
    const int lane = tid & 31;
    const int g  = lane >> 2;
    const int t4 = lane & 3;
    const int wm = (tid >> 5) >> 1;
    const int wn = (tid >> 5) & 1;
    const int m0 = blockIdx.x * 128;
    const int n0 = blockIdx.y * 128;

    float acc[4][8][4] = {};
    gemm_mainloop(g_C, g_Wo16, smw, m0, n0, tid, acc);

#pragma unroll
    for (int mf = 0; mf < 4; mf++) {
#pragma unroll
        for (int nf = 0; nf < 8; nf++) {
            const int n = n0 + wn * 64 + nf * 8 + 2 * t4;
            const float b0 = bias[n];
            const float b1 = bias[n + 1];
#pragma unroll
            for (int rr = 0; rr < 2; rr++) {
                const int m = m0 + wm * 64 + mf * 16 + g + rr * 8;
                *(float2*)(Cout + (size_t)m * D_ + n) =
                    make_float2(acc[mf][nf][2 * rr + 0] + b0,
                                acc[mf][nf][2 * rr + 1] + b1);
            }
        }
    }
}

// ---------------------------------------------------------------------------
// Fused flash attention, fp16 m16n8k16, ldmatrix operand loads.
// CTA: 256 queries x one (b,h). 8 warps x 32 query rows.
// The S->P permute vanishes (A-fragment cols == S-accumulator cols).
// K tile [key][d] halves, V transposed [d][key]; stride 36 words.
// Scores in log2 domain (log2e folded into Q scale); ex2 softmax.
// Masked rows: scale 0 -> uniform softmax == reference (-1e9 rows).
// ---------------------------------------------------------------------------
#define TQ 256
#define TK 64
#define AT_STR 36
#define KV_WORDS (64 * AT_STR)             // 2304 words per K or V tile
#define BUF_WORDS (2 * KV_WORDS)           // K + V per buffer

__global__ __launch_bounds__(256, 1) void attn_kernel(const int* __restrict__ mask)
{
    extern __shared__ uint32_t sm[];

    const int tid  = threadIdx.x;
    const int lane = tid & 31;
    const int wid  = tid >> 5;
    const int g    = lane >> 2;
    const int t4   = lane & 3;
    const int q0   = blockIdx.x * TQ;
    const int bh   = blockIdx.y;
    const int b    = bh / H_;
    const int h    = bh - b * H_;

    const uint32_t* Qg = g_Q + (size_t)bh * S_ * (DK_ / 2);
    const uint32_t* Kg = g_K + (size_t)bh * S_ * (DK_ / 2);
    const uint32_t* Vg = g_V + (size_t)bh * DK_ * (S_ / 2);   // [dk][s/2]

    const uint32_t smem_base = smem_u32(sm);

    // ldmatrix per-lane addressing
    const int rowoff = lane & 7;
    const int selb   = (lane >> 3) & 1;

    // copy mapping: 64 rows x 32 words per tile; 256 threads: 8 words each
    const int crow = tid >> 2;          // 0..63
    const int ccol = (tid & 3) * 8;     // 0,8,16,24

    int row[2][2];
    float sc[2][2];
#pragma unroll
    for (int mb = 0; mb < 2; mb++)
#pragma unroll
        for (int rr = 0; rr < 2; rr++) {
            row[mb][rr] = wid * 32 + mb * 16 + g + rr * 8;
            // 1/sqrt(64) * log2(e): scores land in log2 domain
            sc[mb][rr] = mask[b * S_ + q0 + row[mb][rr]] ? 0.18033688011112042f : 0.0f;
        }

    // Q fragments (fp16 pairs, scale folded in)
    uint32_t qa[4][2][4];
#pragma unroll
    for (int kf = 0; kf < 4; kf++)
#pragma unroll
        for (int mb = 0; mb < 2; mb++) {
#pragma unroll
            for (int rr = 0; rr < 2; rr++) {
                const uint32_t* qrow = Qg + (size_t)(q0 + row[mb][rr]) * (DK_ / 2);
                uint32_t w0 = qrow[kf * 8 + t4];
                uint32_t w1 = qrow[kf * 8 + t4 + 4];
                float2 f0 = __half22float2(*(__half2*)&w0);
                float2 f1 = __half22float2(*(__half2*)&w1);
                qa[kf][mb][rr]     = f2h2(f0.x * sc[mb][rr], f0.y * sc[mb][rr]);
                qa[kf][mb][rr + 2] = f2h2(f1.x * sc[mb][rr], f1.y * sc[mb][rr]);
            }
        }

    float mr[2][2], l[2][2];
    float oacc[2][8][4] = {};
#pragma unroll
    for (int mb = 0; mb < 2; mb++)
#pragma unroll
        for (int rr = 0; rr < 2; rr++) { mr[mb][rr] = -1e30f; l[mb][rr] = 0.0f; }

    auto issue_tile = [&](int buf, int k0) {
        const uint32_t kdst = smem_base + (buf * BUF_WORDS + crow * AT_STR + ccol) * 4;
        const uint32_t vdst = kdst + KV_WORDS * 4;
        const uint32_t* ksrc = Kg + (size_t)(k0 + crow) * (DK_ / 2) + ccol;
        const uint32_t* vsrc = Vg + (size_t)crow * (S_ / 2) + k0 / 2 + ccol;
        cpasync16(kdst, ksrc);
        cpasync16(kdst + 16, ksrc + 4);
        cpasync16(vdst, vsrc);
        cpasync16(vdst + 16, vsrc + 4);
    };

    issue_tile(0, 0);
    CP_COMMIT();

    const int nT = S_ / TK;
    for (int t = 0; t < nT; t++) {
        CP_WAIT0();
        __syncthreads();
        if (t + 1 < nT) {
            issue_tile((t + 1) & 1, (t + 1) * TK);
            CP_COMMIT();
        }

        const uint32_t kbase = smem_base + ((t & 1) * BUF_WORDS) * 4;
        const uint32_t vbase = kbase + KV_WORDS * 4;

        // S = Q @ K^T  (warp: 32 rows x 64 keys; 4 k16 steps)
        float sacc[2][8][4] = {};
#pragma unroll
        for (int kf = 0; kf < 4; kf++) {
            uint32_t kb[8][2];
#pragma unroll
            for (int nf = 0; nf < 8; nf++)
                ldmx2(kb[nf], kbase +
                      ((uint32_t)((nf * 8 + rowoff) * AT_STR + kf * 8 + selb * 4)) * 4);
#pragma unroll
            for (int nf = 0; nf < 8; nf++) {
                mma16(sacc[0][nf], qa[kf][0], kb[nf]);
                mma16(sacc[1][nf], qa[kf][1], kb[nf]);
            }
        }

        // Online softmax (log2 domain; quad reduce)
#pragma unroll
        for (int mb = 0; mb < 2; mb++) {
            float mx0 = -1e30f, mx1 = -1e30f;
#pragma unroll
            for (int nf = 0; nf < 8; nf++) {
                mx0 = fmaxf(mx0, fmaxf(sacc[mb][nf][0], sacc[mb][nf][1]));
                mx1 = fmaxf(mx1, fmaxf(sacc[mb][nf][2], sacc[mb][nf][3]));
            }
            mx0 = fmaxf(mx0, __shfl_xor_sync(0xffffffffu, mx0, 1));
            mx0 = fmaxf(mx0, __shfl_xor_sync(0xffffffffu, mx0, 2));
            mx1 = fmaxf(mx1, __shfl_xor_sync(0xffffffffu, mx1, 1));
            mx1 = fmaxf(mx1, __shfl_xor_sync(0xffffffffu, mx1, 2));

            const float mn0 = fmaxf(mr[mb][0], mx0);
            const float mn1 = fmaxf(mr[mb][1], mx1);
            const float c0 = ex2f(mr[mb][0] - mn0);
            const float c1 = ex2f(mr[mb][1] - mn1);
            mr[mb][0] = mn0; mr[mb][1] = mn1;

            float s0 = 0.0f, s1 = 0.0f;
#pragma unroll
            for (int nf = 0; nf < 8; nf++) {
                sacc[mb][nf][0] = ex2f(sacc[mb][nf][0] - mn0);
                sacc[mb][nf][1] = ex2f(sacc[mb][nf][1] - mn0);
                sacc[mb][nf][2] = ex2f(sacc[mb][nf][2] - mn1);
                sacc[mb][nf][3] = ex2f(sacc[mb][nf][3] - mn1);
                s0 += sacc[mb][nf][0] + sacc[mb][nf][1];
                s1 += sacc[mb][nf][2] + sacc[mb][nf][3];
            }
            s0 += __shfl_xor_sync(0xffffffffu, s0, 1);
            s0 += __shfl_xor_sync(0xffffffffu, s0, 2);
            s1 += __shfl_xor_sync(0xffffffffu, s1, 1);
            s1 += __shfl_xor_sync(0xffffffffu, s1, 2);
            l[mb][0] = l[mb][0] * c0 + s0;
            l[mb][1] = l[mb][1] * c1 + s1;

#pragma unroll
            for (int nf = 0; nf < 8; nf++) {
                oacc[mb][nf][0] *= c0; oacc[mb][nf][1] *= c0;
                oacc[mb][nf][2] *= c1; oacc[mb][nf][3] *= c1;
            }
        }

        // O += P @ V. fp16 A-fragment cols == S-accumulator cols: pure packs.
#pragma unroll
        for (int kf = 0; kf < 4; kf++) {
            uint32_t pa[2][4];
#pragma unroll
            for (int mb = 0; mb < 2; mb++) {
                pa[mb][0] = f2h2(sacc[mb][2 * kf][0],     sacc[mb][2 * kf][1]);
                pa[mb][1] = f2h2(sacc[mb][2 * kf][2],     sacc[mb][2 * kf][3]);
                pa[mb][2] = f2h2(sacc[mb][2 * kf + 1][0], sacc[mb][2 * kf + 1][1]);
                pa[mb][3] = f2h2(sacc[mb][2 * kf + 1][2], sacc[mb][2 * kf + 1][3]);
            }
            uint32_t vb[8][2];
#pragma unroll
            for (int nf = 0; nf < 8; nf++)
                ldmx2(vb[nf], vbase +
                      ((uint32_t)((nf * 8 + rowoff) * AT_STR + kf * 8 + selb * 4)) * 4);
#pragma unroll
            for (int nf = 0; nf < 8; nf++) {
                mma16(oacc[0][nf], pa[0], vb[nf]);
                mma16(oacc[1][nf], pa[1], vb[nf]);
            }
        }
    }

    // Epilogue: normalize, write fp16 pairs in concat [b, s, d] layout
#pragma unroll
    for (int mb = 0; mb < 2; mb++) {
        const float inv0 = 1.0f / l[mb][0];
        const float inv1 = 1.0f / l[mb][1];
        const size_t b0w = ((size_t)b * S_ + q0 + row[mb][0]) * DW + h * (DK_ / 2);
        const size_t b1w = ((size_t)b * S_ + q0 + row[mb][1]) * DW + h * (DK_ / 2);
#pragma unroll
        for (int nf = 0; nf < 8; nf++) {
            g_C[b0w + nf * 4 + t4] = f2h2(oacc[mb][nf][0] * inv0, oacc[mb][nf][1] * inv0);
            g_C[b1w + nf * 4 + t4] = f2h2(oacc[mb][nf][2] * inv1, oacc[mb][nf][3] * inv1);
        }
    }
}

// ---------------------------------------------------------------------------
extern "C" void kernel_launch(void* const* d_in, const int* in_sizes, int n_in,
                              void* d_out, int out_size)
{
    const float* q    = (const float*)d_in[0];
    const float* k    = (const float*)d_in[1];
    const float* v    = (const float*)d_in[2];
    const int*   mask = (const int*)  d_in[3];
    const float* Wq   = (const float*)d_in[4];
    const float* bq   = (const float*)d_in[5];
    const float* Wk   = (const float*)d_in[6];
    const float* bk   = (const float*)d_in[7];
    const float* Wv   = (const float*)d_in[8];
    const float* bv   = (const float*)d_in[9];
    const float* Wo   = (const float*)d_in[10];
    const float* bo   = (const float*)d_in[11];
    float* out = (float*)d_out;

    const int gemm_smem = 2 * G_BUF * (int)sizeof(uint32_t);  // 73728 B
    cudaFuncSetAttribute(gemm_proj_kernel, cudaFuncAttributeMaxDynamicSharedMemorySize, gemm_smem);
    cudaFuncSetAttribute(gemm_out_kernel,  cudaFuncAttributeMaxDynamicSharedMemorySize, gemm_smem);

    // Pre-pass: fp32 -> fp16 for inputs + weights
    cvt_kernel<<<dim3(2048, 7), dim3(256)>>>(q, k, v, Wq, Wk, Wv, Wo);

    // Fused Q/K/V projections (fp16 MMA + ldmatrix)
    gemm_proj_kernel<<<dim3(M_ / 128, D_ / 128, 3), dim3(128), gemm_smem>>>(bq, bk, bv);

    // Fused attention (fp16 MMA + ldmatrix) -> fp16 concat layout
    const int smem = 2 * BUF_WORDS * (int)sizeof(uint32_t);  // 36864 B
    cudaFuncSetAttribute(attn_kernel, cudaFuncAttributeMaxDynamicSharedMemorySize, smem);
    attn_kernel<<<dim3(S_ / TQ, B_ * H_), dim3(256), smem>>>(mask);

    // Output projection (fp16 MMA + ldmatrix, fp32 out)
    gemm_out_kernel<<<dim3(M_ / 128, D_ / 128), dim3(128), gemm_smem>>>(bo, out);
}

// round 16
// speedup vs baseline: 1.9676x; 1.0182x over previous
#include <cuda_runtime.h>
#include <cuda_fp16.h>
#include <cstdint>

// Problem constants
#define B_  4
#define S_  2048
#define D_  768
#define H_  12
#define DK_ 64
#define M_  (B_ * S_)   // 8192
#define DW  (D_ / 2)    // 384 words (half-pairs) per row

// Scratch (module-static device memory; no runtime allocation)
// Pre-converted fp16 copies (packed half2 per uint32):
__device__ uint32_t g_q16[(size_t)M_ * DW];
__device__ uint32_t g_k16[(size_t)M_ * DW];
__device__ uint32_t g_v16[(size_t)M_ * DW];
__device__ uint32_t g_Wq16[(size_t)D_ * DW];
__device__ uint32_t g_Wk16[(size_t)D_ * DW];
__device__ uint32_t g_Wv16[(size_t)D_ * DW];
__device__ uint32_t g_Wo16[(size_t)D_ * DW];
// Q,K fp16 [b,h,s,dk]; V fp16 TRANSPOSED [b,h,dk,s]; C fp16 concat [b,s,d].
__device__ uint32_t g_Q[(size_t)B_ * H_ * S_ * DK_ / 2];
__device__ uint32_t g_K[(size_t)B_ * H_ * S_ * DK_ / 2];
__device__ uint32_t g_V[(size_t)B_ * H_ * DK_ * S_ / 2];
__device__ uint32_t g_C[(size_t)M_ * DW];

// ---------------------------------------------------------------------------
// Helpers
// ---------------------------------------------------------------------------
__device__ __forceinline__ uint32_t f2h2(float a, float b) {
    __half2 h = __floats2half2_rn(a, b);   // low = a, high = b
    return *(uint32_t*)&h;
}
__device__ __forceinline__ float ex2f(float x) {
    float r;
    asm("ex2.approx.f32 %0, %1;" : "=f"(r) : "f"(x));
    return r;
}
// Packed half2 2^x (one MUFU op for two values)
__device__ __forceinline__ uint32_t ex2h2(uint32_t x) {
    uint32_t r;
    asm("ex2.approx.f16x2 %0, %1;" : "=r"(r) : "r"(x));
    return r;
}
// D += A(16x16 row) * B(16x8 col), fp16 inputs, fp32 accumulate
__device__ __forceinline__ void mma16(float* c, const uint32_t* a, const uint32_t* b) {
    asm volatile(
        "mma.sync.aligned.m16n8k16.row.col.f32.f16.f16.f32 "
        "{%0,%1,%2,%3},{%4,%5,%6,%7},{%8,%9},{%0,%1,%2,%3};"
        : "+f"(c[0]), "+f"(c[1]), "+f"(c[2]), "+f"(c[3])
        : "r"(a[0]), "r"(a[1]), "r"(a[2]), "r"(a[3]), "r"(b[0]), "r"(b[1]));
}
__device__ __forceinline__ uint32_t smem_u32(const void* p) {
    uint32_t a;
    asm("{ .reg .u64 t; cvta.to.shared.u64 t, %1; cvt.u32.u64 %0, t; }" : "=r"(a) : "l"(p));
    return a;
}
__device__ __forceinline__ void cpasync16(uint32_t dst, const void* src) {
    asm volatile("cp.async.cg.shared.global [%0], [%1], 16;" :: "r"(dst), "l"(src));
}
#define CP_COMMIT() asm volatile("cp.async.commit_group;" ::: "memory")
#define CP_WAIT0()  asm volatile("cp.async.wait_group 0;" ::: "memory")

// ldmatrix: 4 / 2 m8n8 b16 matrices.
__device__ __forceinline__ void ldmx4(uint32_t* r, uint32_t addr) {
    asm volatile("ldmatrix.sync.aligned.m8n8.x4.shared.b16 {%0,%1,%2,%3}, [%4];"
                 : "=r"(r[0]), "=r"(r[1]), "=r"(r[2]), "=r"(r[3]) : "r"(addr));
}
__device__ __forceinline__ void ldmx2(uint32_t* r, uint32_t addr) {
    asm volatile("ldmatrix.sync.aligned.m8n8.x2.shared.b16 {%0,%1}, [%2];"
                 : "=r"(r[0]), "=r"(r[1]) : "r"(addr));
}

// ---------------------------------------------------------------------------
// Pre-pass: fp32 -> packed fp16. blockIdx.y selects array.
// ---------------------------------------------------------------------------
__global__ __launch_bounds__(256) void cvt_kernel(
    const float* __restrict__ q, const float* __restrict__ k,
    const float* __restrict__ v,
    const float* __restrict__ Wq, const float* __restrict__ Wk,
    const float* __restrict__ Wv, const float* __restrict__ Wo)
{
    const int z = blockIdx.y;
    const float* src;
    uint32_t* dst;
    int n;
    switch (z) {
        case 0: src = q;  dst = g_q16;  n = M_ * D_; break;
        case 1: src = k;  dst = g_k16;  n = M_ * D_; break;
        case 2: src = v;  dst = g_v16;  n = M_ * D_; break;
        case 3: src = Wq; dst = g_Wq16; n = D_ * D_; break;
        case 4: src = Wk; dst = g_Wk16; n = D_ * D_; break;
        case 5: src = Wv; dst = g_Wv16; n = D_ * D_; break;
        default: src = Wo; dst = g_Wo16; n = D_ * D_; break;
    }
    const int stride = gridDim.x * blockDim.x * 4;
    for (int i = (blockIdx.x * blockDim.x + threadIdx.x) * 4; i < n; i += stride) {
        const float4 s = *(const float4*)(src + i);
        *(uint2*)(dst + i / 2) = make_uint2(f2h2(s.x, s.y), f2h2(s.z, s.w));
    }
}

// ---------------------------------------------------------------------------
// fp16 GEMM core: acc = A[128 rows]@W[128 rows]^T over K=768.
// BM=128, BN=128, BK=64 halves (32 words), 12 chunks. 128 threads = 4 warps
// (2x2), warp tile 64x64. cp.async(.cg) double-buffered. Stride 36 words:
// ldmatrix-conflict-free (row stride == 4 banks). Fragments via ldmatrix.
// ---------------------------------------------------------------------------
#define G_STR 36
#define G_ARR (128 * G_STR)        // words per A or B tile
#define G_BUF (2 * G_ARR)          // A + B per buffer

__device__ __forceinline__ void gemm_mainloop(
    const uint32_t* __restrict__ A, const uint32_t* __restrict__ W,
    uint32_t* smf, int m0, int n0, int tid, float acc[4][8][4])
{
    const uint32_t smem_base = smem_u32(smf);
    const int lane = tid & 31;
    const int wid  = tid >> 5;
    const int wm   = wid >> 1;
    const int wn   = wid & 1;
    const int ro = tid >> 3;          // 0..15
    const int ch = (tid & 7) * 4;     // 0..28 (words)

    // ldmatrix per-lane addressing
    const int rowoff = lane & 7;
    const int sel    = lane >> 3;          // 0..3 (x4: matrix index)
    const int selb   = sel & 1;            // x2: matrix index

    auto issue = [&](int buf, int k0w) {
#pragma unroll
        for (int i = 0; i < 8; i++) {
            const int r = ro + i * 16;
            cpasync16(smem_base + (buf * G_BUF + r * G_STR + ch) * 4,
                      A + (size_t)(m0 + r) * DW + k0w + ch);
            cpasync16(smem_base + (buf * G_BUF + G_ARR + r * G_STR + ch) * 4,
                      W + (size_t)(n0 + r) * DW + k0w + ch);
        }
    };

    issue(0, 0);
    CP_COMMIT();

    const int nC = 12;
    for (int c = 0; c < nC; c++) {
        CP_WAIT0();
        __syncthreads();
        if (c + 1 < nC) {
            issue((c + 1) & 1, (c + 1) * 32);
            CP_COMMIT();
        }

        const uint32_t abase = smem_base + ((c & 1) * G_BUF) * 4;
        const uint32_t bbase = abase + G_ARR * 4;

#pragma unroll
        for (int kf = 0; kf < 4; kf++) {
            uint32_t a[4][4];
#pragma unroll
            for (int mf = 0; mf < 4; mf++) {
                const int r = wm * 64 + mf * 16 + (sel & 1) * 8 + rowoff;
                ldmx4(a[mf], abase + ((uint32_t)(r * G_STR + kf * 8 + (sel >> 1) * 4)) * 4);
            }
            uint32_t bf[8][2];
#pragma unroll
            for (int nf = 0; nf < 8; nf++) {
                const int r = wn * 64 + nf * 8 + rowoff;
                ldmx2(bf[nf], bbase + ((uint32_t)(r * G_STR + kf * 8 + selb * 4)) * 4);
            }
#pragma unroll
            for (int nf = 0; nf < 8; nf++)
#pragma unroll
                for (int mf = 0; mf < 4; mf++)
                    mma16(acc[mf][nf], a[mf], bf[nf]);
        }
    }
}

// Fused Q/K/V projection: z selects operand set.
// z=0,1 (Q,K): fp16 [b,h,s,dk]; z=2 (V): fp16 [b,h,dk,s].
__global__ __launch_bounds__(128, 2) void gemm_proj_kernel(
    const float* __restrict__ bq, const float* __restrict__ bk,
    const float* __restrict__ bv)
{
    extern __shared__ uint32_t smw[];
    const int z = blockIdx.z;
    const uint32_t* A    = (z == 0) ? g_q16  : (z == 1) ? g_k16  : g_v16;
    const uint32_t* W    = (z == 0) ? g_Wq16 : (z == 1) ? g_Wk16 : g_Wv16;
    const float*    bias = (z == 0) ? bq     : (z == 1) ? bk     : bv;
    uint32_t*       Cout = (z == 0) ? g_Q    : (z == 1) ? g_K    : g_V;

    const int tid = threadIdx.x;
    const int lane = tid & 31;
    const int g  = lane >> 2;
    const int t4 = lane & 3;
    const int wm = (tid >> 5) >> 1;
    const int wn = (tid >> 5) & 1;
    const int m0 = blockIdx.x * 128;
    const int n0 = blockIdx.y * 128;

    float acc[4][8][4] = {};
    gemm_mainloop(A, W, smw, m0, n0, tid, acc);

#pragma unroll
    for (int mf = 0; mf < 4; mf++) {
#pragma unroll
        for (int nf = 0; nf < 8; nf++) {
            const int n = n0 + wn * 64 + nf * 8 + 2 * t4;
            const float b0 = bias[n];
            const float b1 = bias[n + 1];
#pragma unroll
            for (int rr = 0; rr < 2; rr++) {
                const int m = m0 + wm * 64 + mf * 16 + g + rr * 8;
                const float ox = acc[mf][nf][2 * rr + 0] + b0;
                const float oy = acc[mf][nf][2 * rr + 1] + b1;
                const int bidx = m >> 11;
                const int srow = m & (S_ - 1);
                const int h    = n >> 6;
                const int dk   = n & 63;
                if (z < 2) {
                    Cout[(((size_t)(bidx * H_ + h)) * S_ + srow) * (DK_ / 2) + dk / 2] =
                        f2h2(ox, oy);
                } else {
                    __half* Vh = (__half*)Cout;
                    const size_t base = ((size_t)(bidx * H_ + h)) * DK_;
                    Vh[(base + dk) * S_ + srow]     = __float2half_rn(ox);
                    Vh[(base + dk + 1) * S_ + srow] = __float2half_rn(oy);
                }
            }
        }
    }
}

// Output projection: reads fp16 C and Wo, fp32 out [M, D].
__global__ __launch_bounds__(128, 2) void gemm_out_kernel(
    const float* __restrict__ bias, float* __restrict__ Cout)
{
    extern __shared__ uint32_t smw[];
    const int tid = threadIdx.x;
    const int lane = tid & 31;
    const int g  = lane >> 2;
    const int t4 = lane & 3;
    const int wm = (tid >> 5) >> 1;
    const int wn = (tid >> 5) & 1;
    const int m0 = blockIdx.x * 128;
    const int n0 = blockIdx.y * 128;

    float acc[4][8][4] = {};
    gemm_mainloop(g_C, g_Wo16, smw, m0, n0, tid, acc);

#pragma unroll
    for (int mf = 0; mf < 4; mf++) {
#pragma unroll
        for (int nf = 0; nf < 8; nf++) {
            const int n = n0 + wn * 64 + nf * 8 + 2 * t4;
            const float b0 = bias[n];
            const float b1 = bias[n + 1];
#pragma unroll
            for (int rr = 0; rr < 2; rr++) {
                const int m = m0 + wm * 64 + mf * 16 + g + rr * 8;
                *(float2*)(Cout + (size_t)m * D_ + n) =
                    make_float2(acc[mf][nf][2 * rr + 0] + b0,
                                acc[mf][nf][2 * rr + 1] + b1);
            }
        }
    }
}

// ---------------------------------------------------------------------------
// Fused flash attention, fp16 m16n8k16, ldmatrix operand loads.
// CTA: 256 queries x one (b,h). 8 warps x 32 query rows.
// Softmax exp via ex2.approx.f16x2: one MUFU op per half2 pair, and the
// outputs ARE the fp16 P-fragment words (pa = register renames of ph).
// Row sums unpacked to fp32 (FMA pipe). Corrections stay fp32 ex2.
// K tile [key][d] halves, V transposed [d][key]; stride 36 words.
// Scores in log2 domain (log2e folded into Q scale).
// Masked rows: scale 0 -> uniform softmax == reference (-1e9 rows).
// ---------------------------------------------------------------------------
#define TQ 256
#define TK 64
#define AT_STR 36
#define KV_WORDS (64 * AT_STR)             // 2304 words per K or V tile
#define BUF_WORDS (2 * KV_WORDS)           // K + V per buffer

__global__ __launch_bounds__(256, 1) void attn_kernel(const int* __restrict__ mask)
{
    extern __shared__ uint32_t sm[];

    const int tid  = threadIdx.x;
    const int lane = tid & 31;
    const int wid  = tid >> 5;
    const int g    = lane >> 2;
    const int t4   = lane & 3;
    const int q0   = blockIdx.x * TQ;
    const int bh   = blockIdx.y;
    const int b    = bh / H_;
    const int h    = bh - b * H_;

    const uint32_t* Qg = g_Q + (size_t)bh * S_ * (DK_ / 2);
    const uint32_t* Kg = g_K + (size_t)bh * S_ * (DK_ / 2);
    const uint32_t* Vg = g_V + (size_t)bh * DK_ * (S_ / 2);   // [dk][s/2]

    const uint32_t smem_base = smem_u32(sm);

    // ldmatrix per-lane addressing
    const int rowoff = lane & 7;
    const int selb   = (lane >> 3) & 1;

    // copy mapping: 64 rows x 32 words per tile; 256 threads: 8 words each
    const int crow = tid >> 2;          // 0..63
    const int ccol = (tid & 3) * 8;     // 0,8,16,24

    int row[2][2];
    float sc[2][2];
#pragma unroll
    for (int mb = 0; mb < 2; mb++)
#pragma unroll
        for (int rr = 0; rr < 2; rr++) {
            row[mb][rr] = wid * 32 + mb * 16 + g + rr * 8;
            // 1/sqrt(64) * log2(e): scores land in log2 domain
            sc[mb][rr] = mask[b * S_ + q0 + row[mb][rr]] ? 0.18033688011112042f : 0.0f;
        }

    // Q fragments (fp16 pairs, scale folded in)
    uint32_t qa[4][2][4];
#pragma unroll
    for (int kf = 0; kf < 4; kf++)
#pragma unroll
        for (int mb = 0; mb < 2; mb++) {
#pragma unroll
            for (int rr = 0; rr < 2; rr++) {
                const uint32_t* qrow = Qg + (size_t)(q0 + row[mb][rr]) * (DK_ / 2);
                uint32_t w0 = qrow[kf * 8 + t4];
                uint32_t w1 = qrow[kf * 8 + t4 + 4];
                float2 f0 = __half22float2(*(__half2*)&w0);
                float2 f1 = __half22float2(*(__half2*)&w1);
                qa[kf][mb][rr]     = f2h2(f0.x * sc[mb][rr], f0.y * sc[mb][rr]);
                qa[kf][mb][rr + 2] = f2h2(f1.x * sc[mb][rr], f1.y * sc[mb][rr]);
            }
        }

    float mr[2][2], l[2][2];
    float oacc[2][8][4] = {};
#pragma unroll
    for (int mb = 0; mb < 2; mb++)
#pragma unroll
        for (int rr = 0; rr < 2; rr++) { mr[mb][rr] = -1e30f; l[mb][rr] = 0.0f; }

    auto issue_tile = [&](int buf, int k0) {
        const uint32_t kdst = smem_base + (buf * BUF_WORDS + crow * AT_STR + ccol) * 4;
        const uint32_t vdst = kdst + KV_WORDS * 4;
        const uint32_t* ksrc = Kg + (size_t)(k0 + crow) * (DK_ / 2) + ccol;
        const uint32_t* vsrc = Vg + (size_t)crow * (S_ / 2) + k0 / 2 + ccol;
        cpasync16(kdst, ksrc);
        cpasync16(kdst + 16, ksrc + 4);
        cpasync16(vdst, vsrc);
        cpasync16(vdst + 16, vsrc + 4);
    };

    issue_tile(0, 0);
    CP_COMMIT();

    const int nT = S_ / TK;
    for (int t = 0; t < nT; t++) {
        CP_WAIT0();
        __syncthreads();
        if (t + 1 < nT) {
            issue_tile((t + 1) & 1, (t + 1) * TK);
            CP_COMMIT();
        }

        const uint32_t kbase = smem_base + ((t & 1) * BUF_WORDS) * 4;
        const uint32_t vbase = kbase + KV_WORDS * 4;

        // S = Q @ K^T  (warp: 32 rows x 64 keys; 4 k16 steps)
        float sacc[2][8][4] = {};
#pragma unroll
        for (int kf = 0; kf < 4; kf++) {
            uint32_t kb[8][2];
#pragma unroll
            for (int nf = 0; nf < 8; nf++)
                ldmx2(kb[nf], kbase +
                      ((uint32_t)((nf * 8 + rowoff) * AT_STR + kf * 8 + selb * 4)) * 4);
#pragma unroll
            for (int nf = 0; nf < 8; nf++) {
                mma16(sacc[0][nf], qa[kf][0], kb[nf]);
                mma16(sacc[1][nf], qa[kf][1], kb[nf]);
            }
        }

        // Online softmax (log2 domain; quad reduce). P produced directly as
        // fp16 pairs via ex2.approx.f16x2 (ph = the P@V A-fragment words).
        uint32_t ph[2][8][2];
#pragma unroll
        for (int mb = 0; mb < 2; mb++) {
            float mx0 = -1e30f, mx1 = -1e30f;
#pragma unroll
            for (int nf = 0; nf < 8; nf++) {
                mx0 = fmaxf(mx0, fmaxf(sacc[mb][nf][0], sacc[mb][nf][1]));
                mx1 = fmaxf(mx1, fmaxf(sacc[mb][nf][2], sacc[mb][nf][3]));
            }
            mx0 = fmaxf(mx0, __shfl_xor_sync(0xffffffffu, mx0, 1));
            mx0 = fmaxf(mx0, __shfl_xor_sync(0xffffffffu, mx0, 2));
            mx1 = fmaxf(mx1, __shfl_xor_sync(0xffffffffu, mx1, 1));
            mx1 = fmaxf(mx1, __shfl_xor_sync(0xffffffffu, mx1, 2));

            const float mn0 = fmaxf(mr[mb][0], mx0);
            const float mn1 = fmaxf(mr[mb][1], mx1);
            const float c0 = ex2f(mr[mb][0] - mn0);
            const float c1 = ex2f(mr[mb][1] - mn1);
            mr[mb][0] = mn0; mr[mb][1] = mn1;

            float s0 = 0.0f, s1 = 0.0f;
#pragma unroll
            for (int nf = 0; nf < 8; nf++) {
                uint32_t p0 = ex2h2(f2h2(sacc[mb][nf][0] - mn0, sacc[mb][nf][1] - mn0));
                uint32_t p1 = ex2h2(f2h2(sacc[mb][nf][2] - mn1, sacc[mb][nf][3] - mn1));
                ph[mb][nf][0] = p0;
                ph[mb][nf][1] = p1;
                const float2 f0 = __half22float2(*(__half2*)&p0);
                const float2 f1 = __half22float2(*(__half2*)&p1);
                s0 += f0.x + f0.y;
                s1 += f1.x + f1.y;
            }
            s0 += __shfl_xor_sync(0xffffffffu, s0, 1);
            s0 += __shfl_xor_sync(0xffffffffu, s0, 2);
            s1 += __shfl_xor_sync(0xffffffffu, s1, 1);
            s1 += __shfl_xor_sync(0xffffffffu, s1, 2);
            l[mb][0] = l[mb][0] * c0 + s0;
            l[mb][1] = l[mb][1] * c1 + s1;

#pragma unroll
            for (int nf = 0; nf < 8; nf++) {
                oacc[mb][nf][0] *= c0; oacc[mb][nf][1] *= c0;
                oacc[mb][nf][2] *= c1; oacc[mb][nf][3] *= c1;
            }
        }

        // O += P @ V. pa = pure register renames of ph (no packs, no shuffles).
#pragma unroll
        for (int kf = 0; kf < 4; kf++) {
            uint32_t pa[2][4];
#pragma unroll
            for (int mb = 0; mb < 2; mb++) {
                pa[mb][0] = ph[mb][2 * kf][0];
                pa[mb][1] = ph[mb][2 * kf][1];
                pa[mb][2] = ph[mb][2 * kf + 1][0];
                pa[mb][3] = ph[mb][2 * kf + 1][1];
            }
            uint32_t vb[8][2];
#pragma unroll
            for (int nf = 0; nf < 8; nf++)
                ldmx2(vb[nf], vbase +
                      ((uint32_t)((nf * 8 + rowoff) * AT_STR + kf * 8 + selb * 4)) * 4);
#pragma unroll
            for (int nf = 0; nf < 8; nf++) {
                mma16(oacc[0][nf], pa[0], vb[nf]);
                mma16(oacc[1][nf], pa[1], vb[nf]);
            }
        }
    }

    // Epilogue: normalize, write fp16 pairs in concat [b, s, d] layout
#pragma unroll
    for (int mb = 0; mb < 2; mb++) {
        const float inv0 = 1.0f / l[mb][0];
        const float inv1 = 1.0f / l[mb][1];
        const size_t b0w = ((size_t)b * S_ + q0 + row[mb][0]) * DW + h * (DK_ / 2);
        const size_t b1w = ((size_t)b * S_ + q0 + row[mb][1]) * DW + h * (DK_ / 2);
#pragma unroll
        for (int nf = 0; nf < 8; nf++) {
            g_C[b0w + nf * 4 + t4] = f2h2(oacc[mb][nf][0] * inv0, oacc[mb][nf][1] * inv0);
            g_C[b1w + nf * 4 + t4] = f2h2(oacc[mb][nf][2] * inv1, oacc[mb][nf][3] * inv1);
        }
    }
}

// ---------------------------------------------------------------------------
extern "C" void kernel_launch(void* const* d_in, const int* in_sizes, int n_in,
                              void* d_out, int out_size)
{
    const float* q    = (const float*)d_in[0];
    const float* k    = (const float*)d_in[1];
    const float* v    = (const float*)d_in[2];
    const int*   mask = (const int*)  d_in[3];
    const float* Wq   = (const float*)d_in[4];
    const float* bq   = (const float*)d_in[5];
    const float* Wk   = (const float*)d_in[6];
    const float* bk   = (const float*)d_in[7];
    const float* Wv   = (const float*)d_in[8];
    const float* bv   = (const float*)d_in[9];
    const float* Wo   = (const float*)d_in[10];
    const float* bo   = (const float*)d_in[11];
    float* out = (float*)d_out;

    const int gemm_smem = 2 * G_BUF * (int)sizeof(uint32_t);  // 73728 B
    cudaFuncSetAttribute(gemm_proj_kernel, cudaFuncAttributeMaxDynamicSharedMemorySize, gemm_smem);
    cudaFuncSetAttribute(gemm_out_kernel,  cudaFuncAttributeMaxDynamicSharedMemorySize, gemm_smem);

    // Pre-pass: fp32 -> fp16 for inputs + weights
    cvt_kernel<<<dim3(2048, 7), dim3(256)>>>(q, k, v, Wq, Wk, Wv, Wo);

    // Fused Q/K/V projections (fp16 MMA + ldmatrix)
    gemm_proj_kernel<<<dim3(M_ / 128, D_ / 128, 3), dim3(128), gemm_smem>>>(bq, bk, bv);

    // Fused attention (fp16 MMA + ldmatrix + f16x2 softmax) -> fp16 concat
    const int smem = 2 * BUF_WORDS * (int)sizeof(uint32_t);  // 36864 B
    cudaFuncSetAttribute(attn_kernel, cudaFuncAttributeMaxDynamicSharedMemorySize, smem);
    attn_kernel<<<dim3(S_ / TQ, B_ * H_), dim3(256), smem>>>(mask);

    // Output projection (fp16 MMA + ldmatrix, fp32 out)
    gemm_out_kernel<<<dim3(M_ / 128, D_ / 128), dim3(128), gemm_smem>>>(bo, out);
}